// round 10
// baseline (speedup 1.0000x reference)
#include <cuda_runtime.h>
#include <cstdint>

#define BATCH 4
#define SEQ   4096
#define DIM   1024
#define MTOT  (BATCH * SEQ)      // 16384

#define BM 128
#define BN 128
#define BK 32
#define NTHR 256
#define PADS 48                   // smem row stride in floats (conflict-free LDS.128)
#define BUF_FLOATS (BM * PADS)    // 6144 floats = 24576 B per tile buffer
#define BUF_BYTES  (BUF_FLOATS * 4)
#define SMEM_DYN (2 * 2 * BUF_BYTES)   // A0,B0,A1,B1 = 98304 B (2 CTA/SM: 196.6KB)

// Scratch (allocation-free rule: __device__ globals)
__device__ float g_Q[(size_t)MTOT * DIM];
__device__ float g_K[(size_t)MTOT * DIM];
__device__ float g_V[(size_t)MTOT * DIM];          // holds V^T: [DIM][MTOT]
__device__ float g_S[(size_t)BATCH * SEQ * SEQ];
__device__ float g_X[(size_t)MTOT * DIM];          // tf32-rounded x
__device__ float g_Wq[(size_t)DIM * DIM];
__device__ float g_Wk[(size_t)DIM * DIM];
__device__ float g_Wv[(size_t)DIM * DIM];

// ---------------------------------------------------------------------------
static __device__ __forceinline__ uint32_t s2u(const void* p) {
    uint32_t a;
    asm("{ .reg .u64 t; cvta.to.shared.u64 t, %1; cvt.u32.u64 %0, t; }"
        : "=r"(a) : "l"(p));
    return a;
}
static __device__ __forceinline__ uint32_t f2tf32(float f) {
    uint32_t r;
    asm("cvt.rna.tf32.f32 %0, %1;" : "=r"(r) : "f"(f));
    return r;
}
static __device__ __forceinline__ float rtf(float f) {
    return __uint_as_float(f2tf32(f));
}
static __device__ __forceinline__ void cpasync16(uint32_t saddr, const void* gaddr) {
    asm volatile("cp.async.cg.shared.global [%0], [%1], 16;"
                 :: "r"(saddr), "l"(gaddr) : "memory");
}
static __device__ __forceinline__ void cpcommit() {
    asm volatile("cp.async.commit_group;" ::: "memory");
}
static __device__ __forceinline__ void cpwait0() {
    asm volatile("cp.async.wait_group 0;" ::: "memory");
}
static __device__ __forceinline__ void mma_tf32(float* c, uint32_t a0, uint32_t a1,
                                                uint32_t a2, uint32_t a3,
                                                uint32_t b0, uint32_t b1) {
    asm volatile(
        "mma.sync.aligned.m16n8k8.row.col.f32.tf32.tf32.f32 "
        "{%0,%1,%2,%3}, {%4,%5,%6,%7}, {%8,%9}, {%0,%1,%2,%3};"
        : "+f"(c[0]), "+f"(c[1]), "+f"(c[2]), "+f"(c[3])
        : "r"(a0), "r"(a1), "r"(a2), "r"(a3), "r"(b0), "r"(b1));
}

// ---------------------------------------------------------------------------
// Pre-round a tensor to tf32 (rna), float4 granularity.
// ---------------------------------------------------------------------------
__global__ void __launch_bounds__(256)
round_tf32(const float4* __restrict__ in, float4* __restrict__ out, int n4)
{
    int i = blockIdx.x * 256 + threadIdx.x;
    if (i < n4) {
        float4 v = in[i];
        out[i] = make_float4(rtf(v.x), rtf(v.y), rtf(v.z), rtf(v.w));
    }
}

// ---------------------------------------------------------------------------
// tf32 mma.sync NT GEMM: C[m][n] = alpha * sum_k A[m][k] * B[n][k]
// Inputs must already be tf32-rounded. 2-stage cp.async pipeline, one
// __syncthreads per K-chunk. Fragment loads are LDS.128: each v4 at
// k = 16*ks + 4*t4 feeds TWO k8 MMAs via the shared bijection
// t4 -> {4t4, 4t4+1} (MMA even) and t4 -> {4t4+2, 4t4+3} (MMA odd),
// applied identically to A and B (exact reordering of the dot product).
// flags: 1 = causal tile skip (n0 > m0), 2 = transposed epilogue (C[n][m]),
//        4 = causal K bound (kend = m0 + BM), 8 = round output to tf32
// ---------------------------------------------------------------------------
__global__ void __launch_bounds__(NTHR, 2)
gemm_mma(const float* __restrict__ A, const float* __restrict__ B,
         float* __restrict__ C, int K, int lda, int ldb, int ldc,
         long sA, long sB, long sC, float alpha, int flags)
{
    const int m0 = blockIdx.y * BM;
    const int n0 = blockIdx.x * BN;
    if ((flags & 1) && n0 > m0) return;

    A += (long)blockIdx.z * sA;
    B += (long)blockIdx.z * sB;
    C += (long)blockIdx.z * sC;

    extern __shared__ float smf[];
    const uint32_t sa = s2u(smf);

    const int tid  = threadIdx.x;
    const int lane = tid & 31;
    const int w    = tid >> 5;
    const int wm   = (w >> 2) * 64;     // warp tile M origin (0 or 64)
    const int wn   = (w & 3) * 32;      // warp tile N origin (0..96)
    const int g    = lane >> 2;         // 0..7
    const int t4   = lane & 3;          // 0..3

    const int kend = (flags & 4) ? min(K, m0 + BM) : K;
    const int nc   = kend / BK;

    // Global->smem geometry: 4 x 16B cp.async per thread per operand per chunk
    const int lr  = tid >> 3;           // 0..31 base row
    const int lc4 = (tid & 7) * 4;      // float col 0,4,...,28
    const float* Ag[4]; const float* Bg[4];
    uint32_t sob[4];                    // smem byte offset within a buffer
    #pragma unroll
    for (int i = 0; i < 4; i++) {
        const int row = lr + 32 * i;
        Ag[i] = A + (long)(m0 + row) * lda + lc4;
        Bg[i] = B + (long)(n0 + row) * ldb + lc4;
        sob[i] = (uint32_t)(row * PADS + lc4) * 4u;
    }

    float acc[4][4][4];
    #pragma unroll
    for (int i = 0; i < 4; i++)
        #pragma unroll
        for (int j = 0; j < 4; j++)
            #pragma unroll
            for (int k = 0; k < 4; k++) acc[i][j][k] = 0.f;

    // prologue: issue chunk 0 into stage 0
    {
        #pragma unroll
        for (int i = 0; i < 4; i++) {
            cpasync16(sa + sob[i], Ag[i]);
            cpasync16(sa + BUF_BYTES + sob[i], Bg[i]);
            Ag[i] += BK; Bg[i] += BK;
        }
        cpcommit();
    }

    for (int c = 0; c < nc; c++) {
        cpwait0();            // chunk c's copies complete (only group in flight)
        __syncthreads();      // data visible; other stage fully consumed

        if (c + 1 < nc) {     // issue chunk c+1 into the other stage
            const uint32_t st = (uint32_t)((c + 1) & 1) * 2u * BUF_BYTES;
            #pragma unroll
            for (int i = 0; i < 4; i++) {
                cpasync16(sa + st + sob[i], Ag[i]);
                cpasync16(sa + st + BUF_BYTES + sob[i], Bg[i]);
                Ag[i] += BK; Bg[i] += BK;
            }
            cpcommit();
        }

        const float* Au = smf + (c & 1) * 2 * BUF_FLOATS;
        const float* Bu = Au + BUF_FLOATS;
        #pragma unroll
        for (int ks = 0; ks < 2; ks++) {        // two 16-k blocks per chunk
            const int kp = ks * 16 + 4 * t4;    // v4 base (permuted)
            uint4 alo[4], ahi[4], bv[4];
            #pragma unroll
            for (int tm = 0; tm < 4; tm++) {
                const int m = wm + tm * 16 + g;
                alo[tm] = *(const uint4*)(Au + m * PADS + kp);
                ahi[tm] = *(const uint4*)(Au + (m + 8) * PADS + kp);
            }
            #pragma unroll
            for (int tn = 0; tn < 4; tn++) {
                const int n = wn + tn * 8 + g;
                bv[tn] = *(const uint4*)(Bu + n * PADS + kp);
            }
            // MMA even: words {x,y};  MMA odd: words {z,w}
            #pragma unroll
            for (int tm = 0; tm < 4; tm++)
                #pragma unroll
                for (int tn = 0; tn < 4; tn++)
                    mma_tf32(acc[tm][tn], alo[tm].x, ahi[tm].x,
                             alo[tm].y, ahi[tm].y, bv[tn].x, bv[tn].y);
            #pragma unroll
            for (int tm = 0; tm < 4; tm++)
                #pragma unroll
                for (int tn = 0; tn < 4; tn++)
                    mma_tf32(acc[tm][tn], alo[tm].z, ahi[tm].z,
                             alo[tm].w, ahi[tm].w, bv[tn].z, bv[tn].w);
        }
        // next iteration's __syncthreads closes this stage before refill
    }

    // Epilogue. Thread owns (row = wm+tm*16+g[+8], cols = wn+tn*8+t4*2, +1)
    const bool rnd = (flags & 8) != 0;
    if (flags & 2) {
        #pragma unroll
        for (int tm = 0; tm < 4; tm++) {
            const int mA = m0 + wm + tm * 16 + g;
            #pragma unroll
            for (int tn = 0; tn < 4; tn++) {
                const int n = n0 + wn + tn * 8 + t4 * 2;
                float v0 = alpha * acc[tm][tn][0], v1 = alpha * acc[tm][tn][1];
                float v2 = alpha * acc[tm][tn][2], v3 = alpha * acc[tm][tn][3];
                if (rnd) { v0 = rtf(v0); v1 = rtf(v1); v2 = rtf(v2); v3 = rtf(v3); }
                C[(long)n * ldc + mA]           = v0;
                C[(long)(n + 1) * ldc + mA]     = v1;
                C[(long)n * ldc + mA + 8]       = v2;
                C[(long)(n + 1) * ldc + mA + 8] = v3;
            }
        }
    } else {
        #pragma unroll
        for (int tm = 0; tm < 4; tm++) {
            const int mA = m0 + wm + tm * 16 + g;
            #pragma unroll
            for (int tn = 0; tn < 4; tn++) {
                const int n = n0 + wn + tn * 8 + t4 * 2;
                float v0 = alpha * acc[tm][tn][0], v1 = alpha * acc[tm][tn][1];
                float v2 = alpha * acc[tm][tn][2], v3 = alpha * acc[tm][tn][3];
                if (rnd) { v0 = rtf(v0); v1 = rtf(v1); v2 = rtf(v2); v3 = rtf(v3); }
                *(float2*)(C + (long)mA * ldc + n)       = make_float2(v0, v1);
                *(float2*)(C + (long)(mA + 8) * ldc + n) = make_float2(v2, v3);
            }
        }
    }
}

// ---------------------------------------------------------------------------
// Causal row softmax, in place. Writes tf32-rounded P (PV GEMM input) and
// zero-fills (q, 128-tile boundary) so PV's causal K bound reads only zeros.
// ---------------------------------------------------------------------------
__global__ void __launch_bounds__(256)
softmax_causal(float* __restrict__ S_, int S)
{
    const long row = blockIdx.x;            // b*S + q
    const int  q   = (int)(row & (long)(S - 1));
    float* p = S_ + row * (long)S;
    const int n = q + 1;

    __shared__ float buf[SEQ];
    __shared__ float red[256];
    const int tid = threadIdx.x;

    float lmax = -3.4e38f;
    for (int i = tid; i < n; i += 256) {
        float v = p[i];
        buf[i] = v;
        lmax = fmaxf(lmax, v);
    }
    red[tid] = lmax;
    __syncthreads();
    #pragma unroll
    for (int s = 128; s > 0; s >>= 1) {
        if (tid < s) red[tid] = fmaxf(red[tid], red[tid + s]);
        __syncthreads();
    }
    const float m = red[0];
    __syncthreads();

    float lsum = 0.f;
    for (int i = tid; i < n; i += 256) {
        float e = __expf(buf[i] - m);
        buf[i] = e;
        lsum += e;
    }
    red[tid] = lsum;
    __syncthreads();
    #pragma unroll
    for (int s = 128; s > 0; s >>= 1) {
        if (tid < s) red[tid] += red[tid + s];
        __syncthreads();
    }
    const float inv = 1.0f / red[0];
    __syncthreads();

    for (int i = tid; i < n; i += 256) p[i] = rtf(buf[i] * inv);
    const int zend = ((q >> 7) + 1) << 7;   // next multiple of BM=128
    for (int i = n + tid; i < zend; i += 256) p[i] = 0.f;
}

// ---------------------------------------------------------------------------
extern "C" void kernel_launch(void* const* d_in, const int* in_sizes, int n_in,
                              void* d_out, int out_size)
{
    const float* x  = (const float*)d_in[0];
    const float* Wq = (const float*)d_in[1];
    const float* Wk = (const float*)d_in[2];
    const float* Wv = (const float*)d_in[3];
    float* out = (float*)d_out;

    float *Q, *Kd, *Vt, *Sc, *Xr, *Wqr, *Wkr, *Wvr;
    cudaGetSymbolAddress((void**)&Q,   g_Q);
    cudaGetSymbolAddress((void**)&Kd,  g_K);
    cudaGetSymbolAddress((void**)&Vt,  g_V);
    cudaGetSymbolAddress((void**)&Sc,  g_S);
    cudaGetSymbolAddress((void**)&Xr,  g_X);
    cudaGetSymbolAddress((void**)&Wqr, g_Wq);
    cudaGetSymbolAddress((void**)&Wkr, g_Wk);
    cudaGetSymbolAddress((void**)&Wvr, g_Wv);

    cudaFuncSetAttribute(gemm_mma, cudaFuncAttributeMaxDynamicSharedMemorySize,
                         SMEM_DYN);

    // tf32-round all GEMM inputs once
    const int nx4 = (MTOT * DIM) / 4, nw4 = (DIM * DIM) / 4;
    round_tf32<<<(nx4 + 255) / 256, 256>>>((const float4*)x,  (float4*)Xr,  nx4);
    round_tf32<<<(nw4 + 255) / 256, 256>>>((const float4*)Wq, (float4*)Wqr, nw4);
    round_tf32<<<(nw4 + 255) / 256, 256>>>((const float4*)Wk, (float4*)Wkr, nw4);
    round_tf32<<<(nw4 + 255) / 256, 256>>>((const float4*)Wv, (float4*)Wvr, nw4);

    // QKV projections (outputs tf32-rounded); V written transposed (Vt)
    dim3 gP(DIM / BN, MTOT / BM, 1);
    gemm_mma<<<gP, NTHR, SMEM_DYN>>>(Xr, Wqr, Q,  DIM, DIM, DIM, DIM,
                                     0, 0, 0, 1.0f, 8);
    gemm_mma<<<gP, NTHR, SMEM_DYN>>>(Xr, Wkr, Kd, DIM, DIM, DIM, DIM,
                                     0, 0, 0, 1.0f, 8);
    gemm_mma<<<gP, NTHR, SMEM_DYN>>>(Xr, Wvr, Vt, DIM, DIM, DIM, MTOT,
                                     0, 0, 0, 1.0f, 2 | 8);   // transC + round

    // scores = (1/32) * Q K^T per batch, causal tile skip (no rounding)
    const long sQK = (long)SEQ * DIM;
    const long sSS = (long)SEQ * SEQ;
    dim3 gS(SEQ / BN, SEQ / BM, BATCH);
    gemm_mma<<<gS, NTHR, SMEM_DYN>>>(Q, Kd, Sc, DIM, DIM, DIM, SEQ,
                                     sQK, sQK, sSS, 0.03125f, 1);

    softmax_causal<<<BATCH * SEQ, 256>>>(Sc, SEQ);

    // out = P V per batch : NT with B = Vt (ldb = MTOT), causal K bound
    dim3 gPV(DIM / BN, SEQ / BM, BATCH);
    gemm_mma<<<gPV, NTHR, SMEM_DYN>>>(Sc, Vt, out, SEQ, SEQ, MTOT, DIM,
                                      sSS, (long)SEQ, sQK, 1.0f, 4);
}

// round 11
// speedup vs baseline: 1.2747x; 1.2747x over previous
#include <cuda_runtime.h>
#include <cstdint>

#define BATCH 4
#define SEQ   4096
#define DIM   1024
#define MTOT  (BATCH * SEQ)      // 16384

#define BM 128
#define BN 128
#define BK 32
#define NTHR 256
#define PADS 40                   // smem row stride in floats (conflict-free LDS.64)
#define BUF_FLOATS (BM * PADS)    // 5120 floats = 20480 B per tile buffer
#define BUF_BYTES  (BUF_FLOATS * 4)
#define SMEM_DYN (2 * 2 * BUF_BYTES)   // A0,B0,A1,B1 = 81920 B (2 CTA/SM fits)

// Scratch (allocation-free rule: __device__ globals)
__device__ float g_Q[(size_t)MTOT * DIM];
__device__ float g_K[(size_t)MTOT * DIM];
__device__ float g_V[(size_t)MTOT * DIM];          // holds V^T: [DIM][MTOT]
__device__ float g_S[(size_t)BATCH * SEQ * SEQ];
__device__ float g_X[(size_t)MTOT * DIM];          // tf32-rounded x
__device__ float g_W[(size_t)3 * DIM * DIM];       // tf32-rounded [Wq;Wk;Wv]

// ---------------------------------------------------------------------------
static __device__ __forceinline__ uint32_t s2u(const void* p) {
    uint32_t a;
    asm("{ .reg .u64 t; cvta.to.shared.u64 t, %1; cvt.u32.u64 %0, t; }"
        : "=r"(a) : "l"(p));
    return a;
}
static __device__ __forceinline__ uint32_t f2tf32(float f) {
    uint32_t r;
    asm("cvt.rna.tf32.f32 %0, %1;" : "=r"(r) : "f"(f));
    return r;
}
static __device__ __forceinline__ float rtf(float f) {
    return __uint_as_float(f2tf32(f));
}
static __device__ __forceinline__ void cpasync16(uint32_t saddr, const void* gaddr) {
    asm volatile("cp.async.cg.shared.global [%0], [%1], 16;"
                 :: "r"(saddr), "l"(gaddr) : "memory");
}
static __device__ __forceinline__ void cpcommit() {
    asm volatile("cp.async.commit_group;" ::: "memory");
}
static __device__ __forceinline__ void cpwait0() {
    asm volatile("cp.async.wait_group 0;" ::: "memory");
}
static __device__ __forceinline__ void mma_tf32(float* c, uint32_t a0, uint32_t a1,
                                                uint32_t a2, uint32_t a3,
                                                uint32_t b0, uint32_t b1) {
    asm volatile(
        "mma.sync.aligned.m16n8k8.row.col.f32.tf32.tf32.f32 "
        "{%0,%1,%2,%3}, {%4,%5,%6,%7}, {%8,%9}, {%0,%1,%2,%3};"
        : "+f"(c[0]), "+f"(c[1]), "+f"(c[2]), "+f"(c[3])
        : "r"(a0), "r"(a1), "r"(a2), "r"(a3), "r"(b0), "r"(b1));
}

// ---------------------------------------------------------------------------
// Pre-round a tensor to tf32 (rna), float4 granularity.
// ---------------------------------------------------------------------------
__global__ void __launch_bounds__(256)
round_tf32(const float4* __restrict__ in, float4* __restrict__ out, int n4)
{
    int i = blockIdx.x * 256 + threadIdx.x;
    if (i < n4) {
        float4 v = in[i];
        out[i] = make_float4(rtf(v.x), rtf(v.y), rtf(v.z), rtf(v.w));
    }
}

// ---------------------------------------------------------------------------
// tf32 mma.sync NT GEMM: C[m][n] = alpha * sum_k A[m][k] * B[n][k]
// Inputs must already be tf32-rounded. 2-stage cp.async pipeline, one
// __syncthreads per K-chunk. Fragment loads are LDS.64 with the k-pair
// permutation {t4, t4+4} -> {2t4, 2t4+1} applied identically to A and B.
// flags: 1 = causal tile skip (n0 > m0), 2 = transposed epilogue (C[n][m]),
//        4 = causal K bound (kend = m0 + BM), 8 = round output to tf32,
//        16 = fused-QKV output routing (n-tiles 0-7 -> C, 8-15 -> C2,
//             16-23 -> C3 transposed with ldc = MTOT)
// ---------------------------------------------------------------------------
__global__ void __launch_bounds__(NTHR, 2)
gemm_mma(const float* __restrict__ A, const float* __restrict__ B,
         float* __restrict__ C, float* __restrict__ C2, float* __restrict__ C3,
         int K, int lda, int ldb, int ldc,
         long sA, long sB, long sC, float alpha, int flags)
{
    const int m0 = blockIdx.y * BM;
    const int n0 = blockIdx.x * BN;          // B-space n origin
    if ((flags & 1) && n0 > m0) return;

    A += (long)blockIdx.z * sA;
    B += (long)blockIdx.z * sB;

    extern __shared__ float smf[];
    const uint32_t sa = s2u(smf);

    const int tid  = threadIdx.x;
    const int lane = tid & 31;
    const int w    = tid >> 5;
    const int wm   = (w >> 2) * 64;     // warp tile M origin (0 or 64)
    const int wn   = (w & 3) * 32;      // warp tile N origin (0..96)
    const int g    = lane >> 2;         // 0..7
    const int t4   = lane & 3;          // 0..3

    const int kend = (flags & 4) ? min(K, m0 + BM) : K;
    const int nc   = kend / BK;

    // Global->smem geometry: 4 x 16B cp.async per thread per operand per chunk
    const int lr  = tid >> 3;           // 0..31 base row
    const int lc4 = (tid & 7) * 4;      // float col 0,4,...,28
    const float* Ag[4]; const float* Bg[4];
    uint32_t sob[4];                    // smem byte offset within a buffer
    #pragma unroll
    for (int i = 0; i < 4; i++) {
        const int row = lr + 32 * i;
        Ag[i] = A + (long)(m0 + row) * lda + lc4;
        Bg[i] = B + (long)(n0 + row) * ldb + lc4;
        sob[i] = (uint32_t)(row * PADS + lc4) * 4u;
    }

    float acc[4][4][4];
    #pragma unroll
    for (int i = 0; i < 4; i++)
        #pragma unroll
        for (int j = 0; j < 4; j++)
            #pragma unroll
            for (int k = 0; k < 4; k++) acc[i][j][k] = 0.f;

    // prologue: issue chunk 0 into stage 0
    {
        #pragma unroll
        for (int i = 0; i < 4; i++) {
            cpasync16(sa + sob[i], Ag[i]);
            cpasync16(sa + BUF_BYTES + sob[i], Bg[i]);
            Ag[i] += BK; Bg[i] += BK;
        }
        cpcommit();
    }

    for (int c = 0; c < nc; c++) {
        cpwait0();            // chunk c's copies complete (only group in flight)
        __syncthreads();      // data visible; other stage fully consumed

        if (c + 1 < nc) {     // issue chunk c+1 into the other stage
            const uint32_t st = (uint32_t)((c + 1) & 1) * 2u * BUF_BYTES;
            #pragma unroll
            for (int i = 0; i < 4; i++) {
                cpasync16(sa + st + sob[i], Ag[i]);
                cpasync16(sa + st + BUF_BYTES + sob[i], Bg[i]);
                Ag[i] += BK; Bg[i] += BK;
            }
            cpcommit();
        }

        const uint32_t* Au = (const uint32_t*)(smf + (c & 1) * 2 * BUF_FLOATS);
        const uint32_t* Bu = Au + BUF_FLOATS;
        #pragma unroll
        for (int ks = 0; ks < 4; ks++) {
            const int kp = ks * 8 + 2 * t4;     // permuted k pair base
            uint32_t af[4][4];
            #pragma unroll
            for (int tm = 0; tm < 4; tm++) {
                const int m = wm + tm * 16 + g;
                uint2 lo = *(const uint2*)(Au + m * PADS + kp);
                uint2 hi = *(const uint2*)(Au + (m + 8) * PADS + kp);
                af[tm][0] = lo.x; af[tm][2] = lo.y;   // k=2t4, 2t4+1
                af[tm][1] = hi.x; af[tm][3] = hi.y;
            }
            uint32_t bf[4][2];
            #pragma unroll
            for (int tn = 0; tn < 4; tn++) {
                const int n = wn + tn * 8 + g;
                uint2 bv = *(const uint2*)(Bu + n * PADS + kp);
                bf[tn][0] = bv.x; bf[tn][1] = bv.y;
            }
            #pragma unroll
            for (int tm = 0; tm < 4; tm++)
                #pragma unroll
                for (int tn = 0; tn < 4; tn++)
                    mma_tf32(acc[tm][tn], af[tm][0], af[tm][1], af[tm][2],
                             af[tm][3], bf[tn][0], bf[tn][1]);
        }
        // next iteration's __syncthreads closes this stage before refill
    }

    // Output routing
    float* Cc = C;
    int  nc0  = n0;
    int  ldcc = ldc;
    bool trans = (flags & 2) != 0;
    if (flags & 16) {
        const int ci = blockIdx.x >> 3;
        nc0 = (blockIdx.x & 7) * BN;
        if (ci == 1)      Cc = C2;
        else if (ci == 2) { Cc = C3; trans = true; ldcc = MTOT; }
    }
    Cc += (long)blockIdx.z * sC;

    const bool rnd = (flags & 8) != 0;
    if (trans) {
        #pragma unroll
        for (int tm = 0; tm < 4; tm++) {
            const int mA = m0 + wm + tm * 16 + g;
            #pragma unroll
            for (int tn = 0; tn < 4; tn++) {
                const int n = nc0 + wn + tn * 8 + t4 * 2;
                float v0 = alpha * acc[tm][tn][0], v1 = alpha * acc[tm][tn][1];
                float v2 = alpha * acc[tm][tn][2], v3 = alpha * acc[tm][tn][3];
                if (rnd) { v0 = rtf(v0); v1 = rtf(v1); v2 = rtf(v2); v3 = rtf(v3); }
                Cc[(long)n * ldcc + mA]           = v0;
                Cc[(long)(n + 1) * ldcc + mA]     = v1;
                Cc[(long)n * ldcc + mA + 8]       = v2;
                Cc[(long)(n + 1) * ldcc + mA + 8] = v3;
            }
        }
    } else {
        #pragma unroll
        for (int tm = 0; tm < 4; tm++) {
            const int mA = m0 + wm + tm * 16 + g;
            #pragma unroll
            for (int tn = 0; tn < 4; tn++) {
                const int n = nc0 + wn + tn * 8 + t4 * 2;
                float v0 = alpha * acc[tm][tn][0], v1 = alpha * acc[tm][tn][1];
                float v2 = alpha * acc[tm][tn][2], v3 = alpha * acc[tm][tn][3];
                if (rnd) { v0 = rtf(v0); v1 = rtf(v1); v2 = rtf(v2); v3 = rtf(v3); }
                *(float2*)(Cc + (long)mA * ldcc + n)       = make_float2(v0, v1);
                *(float2*)(Cc + (long)(mA + 8) * ldcc + n) = make_float2(v2, v3);
            }
        }
    }
}

// ---------------------------------------------------------------------------
// Causal row softmax, in place. float4 traffic + shuffle reductions.
// Writes tf32-rounded P and zero-fills (q, 128-tile boundary).
// ---------------------------------------------------------------------------
__global__ void __launch_bounds__(256)
softmax_causal(float* __restrict__ S_, int S)
{
    const long row = blockIdx.x;            // b*S + q
    const int  q   = (int)(row & (long)(S - 1));
    float* p = S_ + row * (long)S;
    const int n = q + 1;
    const int n4 = n >> 2;                  // full float4s
    const int nr = n & 3;                   // tail elements

    __shared__ float buf[SEQ];
    __shared__ float red[8];
    float4* const p4   = (float4*)p;
    float4* const buf4 = (float4*)buf;
    const int tid  = threadIdx.x;
    const int lane = tid & 31;
    const int wid  = tid >> 5;

    // pass 1: load + max
    float lmax = -3.4e38f;
    for (int i = tid; i < n4; i += 256) {
        float4 v = p4[i];
        buf4[i] = v;
        lmax = fmaxf(fmaxf(lmax, fmaxf(v.x, v.y)), fmaxf(v.z, v.w));
    }
    if (tid < nr) {
        float v = p[n4 * 4 + tid];
        buf[n4 * 4 + tid] = v;
        lmax = fmaxf(lmax, v);
    }
    #pragma unroll
    for (int s = 16; s > 0; s >>= 1)
        lmax = fmaxf(lmax, __shfl_xor_sync(0xffffffffu, lmax, s));
    if (lane == 0) red[wid] = lmax;
    __syncthreads();
    float m = red[0];
    #pragma unroll
    for (int i = 1; i < 8; i++) m = fmaxf(m, red[i]);
    __syncthreads();

    // pass 2: exp + sum (in smem)
    float lsum = 0.f;
    for (int i = tid; i < n4; i += 256) {
        float4 v = buf4[i];
        v.x = __expf(v.x - m); v.y = __expf(v.y - m);
        v.z = __expf(v.z - m); v.w = __expf(v.w - m);
        buf4[i] = v;
        lsum += (v.x + v.y) + (v.z + v.w);
    }
    if (tid < nr) {
        float e = __expf(buf[n4 * 4 + tid] - m);
        buf[n4 * 4 + tid] = e;
        lsum += e;
    }
    #pragma unroll
    for (int s = 16; s > 0; s >>= 1)
        lsum += __shfl_xor_sync(0xffffffffu, lsum, s);
    if (lane == 0) red[wid] = lsum;
    __syncthreads();
    float tot = 0.f;
    #pragma unroll
    for (int i = 0; i < 8; i++) tot += red[i];
    const float inv = 1.0f / tot;

    // pass 3: normalize + tf32-round + store; zero-fill to tile boundary
    for (int i = tid; i < n4; i += 256) {
        float4 v = buf4[i];
        p4[i] = make_float4(rtf(v.x * inv), rtf(v.y * inv),
                            rtf(v.z * inv), rtf(v.w * inv));
    }
    if (tid < nr) p[n4 * 4 + tid] = rtf(buf[n4 * 4 + tid] * inv);
    const int zend = ((q >> 7) + 1) << 7;   // next multiple of BM=128
    for (int i = n + tid; i < zend; i += 256) p[i] = 0.f;
}

// ---------------------------------------------------------------------------
extern "C" void kernel_launch(void* const* d_in, const int* in_sizes, int n_in,
                              void* d_out, int out_size)
{
    const float* x  = (const float*)d_in[0];
    const float* Wq = (const float*)d_in[1];
    const float* Wk = (const float*)d_in[2];
    const float* Wv = (const float*)d_in[3];
    float* out = (float*)d_out;

    float *Q, *Kd, *Vt, *Sc, *Xr, *Wc;
    cudaGetSymbolAddress((void**)&Q,  g_Q);
    cudaGetSymbolAddress((void**)&Kd, g_K);
    cudaGetSymbolAddress((void**)&Vt, g_V);
    cudaGetSymbolAddress((void**)&Sc, g_S);
    cudaGetSymbolAddress((void**)&Xr, g_X);
    cudaGetSymbolAddress((void**)&Wc, g_W);

    cudaFuncSetAttribute(gemm_mma, cudaFuncAttributeMaxDynamicSharedMemorySize,
                         SMEM_DYN);

    // tf32-round inputs; weights concatenated into g_W = [Wq;Wk;Wv]
    const int nx4 = (MTOT * DIM) / 4, nw4 = (DIM * DIM) / 4;
    round_tf32<<<(nx4 + 255) / 256, 256>>>((const float4*)x,  (float4*)Xr, nx4);
    round_tf32<<<(nw4 + 255) / 256, 256>>>((const float4*)Wq,
                                           (float4*)Wc, nw4);
    round_tf32<<<(nw4 + 255) / 256, 256>>>((const float4*)Wk,
                                           (float4*)(Wc + (size_t)DIM * DIM), nw4);
    round_tf32<<<(nw4 + 255) / 256, 256>>>((const float4*)Wv,
                                           (float4*)(Wc + (size_t)2 * DIM * DIM), nw4);

    // Fused QKV projection: N = 3072 over concatenated weights.
    // n-tiles 0-7 -> Q, 8-15 -> K, 16-23 -> V^T (transposed, ldc=MTOT)
    dim3 gP(3 * DIM / BN, MTOT / BM, 1);
    gemm_mma<<<gP, NTHR, SMEM_DYN>>>(Xr, Wc, Q, Kd, Vt,
                                     DIM, DIM, DIM, DIM,
                                     0, 0, 0, 1.0f, 8 | 16);

    // scores = (1/32) * Q K^T per batch, causal tile skip (no rounding)
    const long sQK = (long)SEQ * DIM;
    const long sSS = (long)SEQ * SEQ;
    dim3 gS(SEQ / BN, SEQ / BM, BATCH);
    gemm_mma<<<gS, NTHR, SMEM_DYN>>>(Q, Kd, Sc, Sc, Sc,
                                     DIM, DIM, DIM, SEQ,
                                     sQK, sQK, sSS, 0.03125f, 1);

    softmax_causal<<<BATCH * SEQ, 256>>>(Sc, SEQ);

    // out = P V per batch : NT with B = Vt (ldb = MTOT), causal K bound
    dim3 gPV(DIM / BN, SEQ / BM, BATCH);
    gemm_mma<<<gPV, NTHR, SMEM_DYN>>>(Sc, Vt, out, out, out,
                                      SEQ, SEQ, MTOT, DIM,
                                      sSS, (long)SEQ, sQK, 1.0f, 4);
}

// round 12
// speedup vs baseline: 1.3458x; 1.0558x over previous
#include <cuda_runtime.h>
#include <cstdint>

#define BATCH 4
#define SEQ   4096
#define DIM   1024
#define MTOT  (BATCH * SEQ)      // 16384

#define BM 128
#define BN 128
#define BK 32
#define NTHR 256
#define PADS 40                   // smem row stride in floats (conflict-free LDS.64)
#define BUF_FLOATS (BM * PADS)    // 5120 floats = 20480 B per tile buffer
#define BUF_BYTES  (BUF_FLOATS * 4)
#define SMEM_DYN (2 * 2 * BUF_BYTES)   // A0,B0,A1,B1 = 81920 B (2 CTA/SM fits)

// Scratch (allocation-free rule: __device__ globals)
__device__ float g_Q[(size_t)MTOT * DIM];
__device__ float g_K[(size_t)MTOT * DIM];
__device__ float g_V[(size_t)MTOT * DIM];          // holds V^T: [DIM][MTOT]
__device__ float g_S[(size_t)BATCH * SEQ * SEQ];
__device__ float g_X[(size_t)MTOT * DIM];          // tf32-rounded x
__device__ float g_W[(size_t)3 * DIM * DIM];       // tf32-rounded [Wq;Wk;Wv]

// ---------------------------------------------------------------------------
static __device__ __forceinline__ uint32_t s2u(const void* p) {
    uint32_t a;
    asm("{ .reg .u64 t; cvta.to.shared.u64 t, %1; cvt.u32.u64 %0, t; }"
        : "=r"(a) : "l"(p));
    return a;
}
static __device__ __forceinline__ uint32_t f2tf32(float f) {
    uint32_t r;
    asm("cvt.rna.tf32.f32 %0, %1;" : "=r"(r) : "f"(f));
    return r;
}
static __device__ __forceinline__ float rtf(float f) {
    return __uint_as_float(f2tf32(f));
}
static __device__ __forceinline__ void cpasync16(uint32_t saddr, const void* gaddr) {
    asm volatile("cp.async.cg.shared.global [%0], [%1], 16;"
                 :: "r"(saddr), "l"(gaddr) : "memory");
}
static __device__ __forceinline__ void cpcommit() {
    asm volatile("cp.async.commit_group;" ::: "memory");
}
static __device__ __forceinline__ void cpwait0() {
    asm volatile("cp.async.wait_group 0;" ::: "memory");
}
static __device__ __forceinline__ void mma_tf32(float* c, uint32_t a0, uint32_t a1,
                                                uint32_t a2, uint32_t a3,
                                                uint32_t b0, uint32_t b1) {
    asm volatile(
        "mma.sync.aligned.m16n8k8.row.col.f32.tf32.tf32.f32 "
        "{%0,%1,%2,%3}, {%4,%5,%6,%7}, {%8,%9}, {%0,%1,%2,%3};"
        : "+f"(c[0]), "+f"(c[1]), "+f"(c[2]), "+f"(c[3])
        : "r"(a0), "r"(a1), "r"(a2), "r"(a3), "r"(b0), "r"(b1));
}

// ---------------------------------------------------------------------------
// Pre-round x to tf32 (rna), float4 granularity.
// ---------------------------------------------------------------------------
__global__ void __launch_bounds__(256)
round_tf32(const float4* __restrict__ in, float4* __restrict__ out, int n4)
{
    int i = blockIdx.x * 256 + threadIdx.x;
    if (i < n4) {
        float4 v = in[i];
        out[i] = make_float4(rtf(v.x), rtf(v.y), rtf(v.z), rtf(v.w));
    }
}

// Round the 3 weight matrices into concatenated g_W in one launch.
__global__ void __launch_bounds__(256)
round_w3(const float4* __restrict__ wq, const float4* __restrict__ wk,
         const float4* __restrict__ wv, float4* __restrict__ out, int n4)
{
    int i = blockIdx.x * 256 + threadIdx.x;
    if (i >= n4) return;
    const float4* src = (blockIdx.y == 0) ? wq : (blockIdx.y == 1) ? wk : wv;
    float4 v = src[i];
    out[(size_t)blockIdx.y * n4 + i] =
        make_float4(rtf(v.x), rtf(v.y), rtf(v.z), rtf(v.w));
}

// ---------------------------------------------------------------------------
// tf32 mma.sync NT GEMM: C[m][n] = alpha * sum_k A[m][k] * B[n][k]
// Inputs must already be tf32-rounded. 2-stage cp.async pipeline, one
// __syncthreads per K-chunk. Fragment loads are LDS.64 with the k-pair
// permutation {t4, t4+4} -> {2t4, 2t4+1} applied identically to A and B.
// flags: 1 = causal tile skip (n0 > m0), 2 = transposed epilogue (C[n][m]),
//        4 = causal K bound (kend = m0 + BM), 8 = round output to tf32,
//        16 = fused-QKV output routing (n-tiles 0-7 -> C, 8-15 -> C2,
//             16-23 -> C3 transposed with ldc = MTOT)
//        32 = reversed m-tile order (longest causal K first; LPT packing)
// ---------------------------------------------------------------------------
__global__ void __launch_bounds__(NTHR, 2)
gemm_mma(const float* __restrict__ A, const float* __restrict__ B,
         float* __restrict__ C, float* __restrict__ C2, float* __restrict__ C3,
         int K, int lda, int ldb, int ldc,
         long sA, long sB, long sC, float alpha, int flags)
{
    const int my = (flags & 32) ? (gridDim.y - 1 - blockIdx.y) : blockIdx.y;
    const int m0 = my * BM;
    const int n0 = blockIdx.x * BN;          // B-space n origin
    if ((flags & 1) && n0 > m0) return;

    A += (long)blockIdx.z * sA;
    B += (long)blockIdx.z * sB;

    extern __shared__ float smf[];
    const uint32_t sa = s2u(smf);

    const int tid  = threadIdx.x;
    const int lane = tid & 31;
    const int w    = tid >> 5;
    const int wm   = (w >> 2) * 64;     // warp tile M origin (0 or 64)
    const int wn   = (w & 3) * 32;      // warp tile N origin (0..96)
    const int g    = lane >> 2;         // 0..7
    const int t4   = lane & 3;          // 0..3

    const int kend = (flags & 4) ? min(K, m0 + BM) : K;
    const int nc   = kend / BK;

    // Global->smem geometry: 4 x 16B cp.async per thread per operand per chunk
    const int lr  = tid >> 3;           // 0..31 base row
    const int lc4 = (tid & 7) * 4;      // float col 0,4,...,28
    const float* Ag[4]; const float* Bg[4];
    uint32_t sob[4];                    // smem byte offset within a buffer
    #pragma unroll
    for (int i = 0; i < 4; i++) {
        const int row = lr + 32 * i;
        Ag[i] = A + (long)(m0 + row) * lda + lc4;
        Bg[i] = B + (long)(n0 + row) * ldb + lc4;
        sob[i] = (uint32_t)(row * PADS + lc4) * 4u;
    }

    float acc[4][4][4];
    #pragma unroll
    for (int i = 0; i < 4; i++)
        #pragma unroll
        for (int j = 0; j < 4; j++)
            #pragma unroll
            for (int k = 0; k < 4; k++) acc[i][j][k] = 0.f;

    // prologue: issue chunk 0 into stage 0
    {
        #pragma unroll
        for (int i = 0; i < 4; i++) {
            cpasync16(sa + sob[i], Ag[i]);
            cpasync16(sa + BUF_BYTES + sob[i], Bg[i]);
            Ag[i] += BK; Bg[i] += BK;
        }
        cpcommit();
    }

    for (int c = 0; c < nc; c++) {
        cpwait0();            // chunk c's copies complete (only group in flight)
        __syncthreads();      // data visible; other stage fully consumed

        if (c + 1 < nc) {     // issue chunk c+1 into the other stage
            const uint32_t st = (uint32_t)((c + 1) & 1) * 2u * BUF_BYTES;
            #pragma unroll
            for (int i = 0; i < 4; i++) {
                cpasync16(sa + st + sob[i], Ag[i]);
                cpasync16(sa + st + BUF_BYTES + sob[i], Bg[i]);
                Ag[i] += BK; Bg[i] += BK;
            }
            cpcommit();
        }

        const uint32_t* Au = (const uint32_t*)(smf + (c & 1) * 2 * BUF_FLOATS);
        const uint32_t* Bu = Au + BUF_FLOATS;
        #pragma unroll
        for (int ks = 0; ks < 4; ks++) {
            const int kp = ks * 8 + 2 * t4;     // permuted k pair base
            uint32_t af[4][4];
            #pragma unroll
            for (int tm = 0; tm < 4; tm++) {
                const int m = wm + tm * 16 + g;
                uint2 lo = *(const uint2*)(Au + m * PADS + kp);
                uint2 hi = *(const uint2*)(Au + (m + 8) * PADS + kp);
                af[tm][0] = lo.x; af[tm][2] = lo.y;   // k=2t4, 2t4+1
                af[tm][1] = hi.x; af[tm][3] = hi.y;
            }
            uint32_t bf[4][2];
            #pragma unroll
            for (int tn = 0; tn < 4; tn++) {
                const int n = wn + tn * 8 + g;
                uint2 bv = *(const uint2*)(Bu + n * PADS + kp);
                bf[tn][0] = bv.x; bf[tn][1] = bv.y;
            }
            #pragma unroll
            for (int tm = 0; tm < 4; tm++)
                #pragma unroll
                for (int tn = 0; tn < 4; tn++)
                    mma_tf32(acc[tm][tn], af[tm][0], af[tm][1], af[tm][2],
                             af[tm][3], bf[tn][0], bf[tn][1]);
        }
        // next iteration's __syncthreads closes this stage before refill
    }

    // Output routing
    float* Cc = C;
    int  nc0  = n0;
    int  ldcc = ldc;
    bool trans = (flags & 2) != 0;
    if (flags & 16) {
        const int ci = blockIdx.x >> 3;
        nc0 = (blockIdx.x & 7) * BN;
        if (ci == 1)      Cc = C2;
        else if (ci == 2) { Cc = C3; trans = true; ldcc = MTOT; }
    }
    Cc += (long)blockIdx.z * sC;

    const bool rnd = (flags & 8) != 0;
    if (trans) {
        #pragma unroll
        for (int tm = 0; tm < 4; tm++) {
            const int mA = m0 + wm + tm * 16 + g;
            #pragma unroll
            for (int tn = 0; tn < 4; tn++) {
                const int n = nc0 + wn + tn * 8 + t4 * 2;
                float v0 = alpha * acc[tm][tn][0], v1 = alpha * acc[tm][tn][1];
                float v2 = alpha * acc[tm][tn][2], v3 = alpha * acc[tm][tn][3];
                if (rnd) { v0 = rtf(v0); v1 = rtf(v1); v2 = rtf(v2); v3 = rtf(v3); }
                Cc[(long)n * ldcc + mA]           = v0;
                Cc[(long)(n + 1) * ldcc + mA]     = v1;
                Cc[(long)n * ldcc + mA + 8]       = v2;
                Cc[(long)(n + 1) * ldcc + mA + 8] = v3;
            }
        }
    } else {
        #pragma unroll
        for (int tm = 0; tm < 4; tm++) {
            const int mA = m0 + wm + tm * 16 + g;
            #pragma unroll
            for (int tn = 0; tn < 4; tn++) {
                const int n = nc0 + wn + tn * 8 + t4 * 2;
                float v0 = alpha * acc[tm][tn][0], v1 = alpha * acc[tm][tn][1];
                float v2 = alpha * acc[tm][tn][2], v3 = alpha * acc[tm][tn][3];
                if (rnd) { v0 = rtf(v0); v1 = rtf(v1); v2 = rtf(v2); v3 = rtf(v3); }
                *(float2*)(Cc + (long)mA * ldcc + n)       = make_float2(v0, v1);
                *(float2*)(Cc + (long)(mA + 8) * ldcc + n) = make_float2(v2, v3);
            }
        }
    }
}

// ---------------------------------------------------------------------------
// Causal row softmax, in place. float4 traffic + shuffle reductions.
// Writes tf32-rounded P and zero-fills (q, 128-tile boundary).
// ---------------------------------------------------------------------------
__global__ void __launch_bounds__(256)
softmax_causal(float* __restrict__ S_, int S)
{
    const long row = blockIdx.x;            // b*S + q
    const int  q   = (int)(row & (long)(S - 1));
    float* p = S_ + row * (long)S;
    const int n = q + 1;
    const int n4 = n >> 2;                  // full float4s
    const int nr = n & 3;                   // tail elements

    __shared__ float buf[SEQ];
    __shared__ float red[8];
    float4* const p4   = (float4*)p;
    float4* const buf4 = (float4*)buf;
    const int tid  = threadIdx.x;
    const int lane = tid & 31;
    const int wid  = tid >> 5;

    // pass 1: load + max
    float lmax = -3.4e38f;
    for (int i = tid; i < n4; i += 256) {
        float4 v = p4[i];
        buf4[i] = v;
        lmax = fmaxf(fmaxf(lmax, fmaxf(v.x, v.y)), fmaxf(v.z, v.w));
    }
    if (tid < nr) {
        float v = p[n4 * 4 + tid];
        buf[n4 * 4 + tid] = v;
        lmax = fmaxf(lmax, v);
    }
    #pragma unroll
    for (int s = 16; s > 0; s >>= 1)
        lmax = fmaxf(lmax, __shfl_xor_sync(0xffffffffu, lmax, s));
    if (lane == 0) red[wid] = lmax;
    __syncthreads();
    float m = red[0];
    #pragma unroll
    for (int i = 1; i < 8; i++) m = fmaxf(m, red[i]);
    __syncthreads();

    // pass 2: exp + sum (in smem)
    float lsum = 0.f;
    for (int i = tid; i < n4; i += 256) {
        float4 v = buf4[i];
        v.x = __expf(v.x - m); v.y = __expf(v.y - m);
        v.z = __expf(v.z - m); v.w = __expf(v.w - m);
        buf4[i] = v;
        lsum += (v.x + v.y) + (v.z + v.w);
    }
    if (tid < nr) {
        float e = __expf(buf[n4 * 4 + tid] - m);
        buf[n4 * 4 + tid] = e;
        lsum += e;
    }
    #pragma unroll
    for (int s = 16; s > 0; s >>= 1)
        lsum += __shfl_xor_sync(0xffffffffu, lsum, s);
    if (lane == 0) red[wid] = lsum;
    __syncthreads();
    float tot = 0.f;
    #pragma unroll
    for (int i = 0; i < 8; i++) tot += red[i];
    const float inv = 1.0f / tot;

    // pass 3: normalize + tf32-round + store; zero-fill to tile boundary
    for (int i = tid; i < n4; i += 256) {
        float4 v = buf4[i];
        p4[i] = make_float4(rtf(v.x * inv), rtf(v.y * inv),
                            rtf(v.z * inv), rtf(v.w * inv));
    }
    if (tid < nr) p[n4 * 4 + tid] = rtf(buf[n4 * 4 + tid] * inv);
    const int zend = ((q >> 7) + 1) << 7;   // next multiple of BM=128
    for (int i = n + tid; i < zend; i += 256) p[i] = 0.f;
}

// ---------------------------------------------------------------------------
extern "C" void kernel_launch(void* const* d_in, const int* in_sizes, int n_in,
                              void* d_out, int out_size)
{
    const float* x  = (const float*)d_in[0];
    const float* Wq = (const float*)d_in[1];
    const float* Wk = (const float*)d_in[2];
    const float* Wv = (const float*)d_in[3];
    float* out = (float*)d_out;

    float *Q, *Kd, *Vt, *Sc, *Xr, *Wc;
    cudaGetSymbolAddress((void**)&Q,  g_Q);
    cudaGetSymbolAddress((void**)&Kd, g_K);
    cudaGetSymbolAddress((void**)&Vt, g_V);
    cudaGetSymbolAddress((void**)&Sc, g_S);
    cudaGetSymbolAddress((void**)&Xr, g_X);
    cudaGetSymbolAddress((void**)&Wc, g_W);

    cudaFuncSetAttribute(gemm_mma, cudaFuncAttributeMaxDynamicSharedMemorySize,
                         SMEM_DYN);

    // tf32-round inputs; weights concatenated into g_W = [Wq;Wk;Wv]
    const int nx4 = (MTOT * DIM) / 4, nw4 = (DIM * DIM) / 4;
    round_tf32<<<(nx4 + 255) / 256, 256>>>((const float4*)x, (float4*)Xr, nx4);
    {
        dim3 gW((nw4 + 255) / 256, 3, 1);
        round_w3<<<gW, 256>>>((const float4*)Wq, (const float4*)Wk,
                              (const float4*)Wv, (float4*)Wc, nw4);
    }

    // Fused QKV projection: N = 3072 over concatenated weights.
    // n-tiles 0-7 -> Q, 8-15 -> K, 16-23 -> V^T (transposed, ldc=MTOT)
    dim3 gP(3 * DIM / BN, MTOT / BM, 1);
    gemm_mma<<<gP, NTHR, SMEM_DYN>>>(Xr, Wc, Q, Kd, Vt,
                                     DIM, DIM, DIM, DIM,
                                     0, 0, 0, 1.0f, 8 | 16);

    // scores = (1/32) * Q K^T per batch, causal tile skip (no rounding)
    const long sQK = (long)SEQ * DIM;
    const long sSS = (long)SEQ * SEQ;
    dim3 gS(SEQ / BN, SEQ / BM, BATCH);
    gemm_mma<<<gS, NTHR, SMEM_DYN>>>(Q, Kd, Sc, Sc, Sc,
                                     DIM, DIM, DIM, SEQ,
                                     sQK, sQK, sSS, 0.03125f, 1);

    softmax_causal<<<BATCH * SEQ, 256>>>(Sc, SEQ);

    // out = P V per batch : NT with B = Vt (ldb = MTOT), causal K bound.
    // Reversed m-tile order (flag 32): longest-K tiles launch first (LPT).
    dim3 gPV(DIM / BN, SEQ / BM, BATCH);
    gemm_mma<<<gPV, NTHR, SMEM_DYN>>>(Sc, Vt, out, out, out,
                                      SEQ, SEQ, MTOT, DIM,
                                      sSS, (long)SEQ, sQK, 1.0f, 4 | 32);
}

// round 13
// speedup vs baseline: 1.4602x; 1.0850x over previous
#include <cuda_runtime.h>
#include <cstdint>

#define BATCH 4
#define SEQ   4096
#define DIM   1024
#define MTOT  (BATCH * SEQ)      // 16384

#define BM 128
#define BN 128
#define BK 32
#define NTHR 256
#define TILE_FLOATS (BM * BK)     // 4096 floats = 16384 B (swizzled, no pad)
#define TILE_BYTES  (TILE_FLOATS * 4)
#define NSTAGE 3
#define SMEM_DYN (NSTAGE * 2 * TILE_BYTES)   // 98304 B -> 2 CTA/SM = 192KB

// Scratch (allocation-free rule: __device__ globals)
__device__ float g_Q[(size_t)MTOT * DIM];
__device__ float g_K[(size_t)MTOT * DIM];
__device__ float g_V[(size_t)MTOT * DIM];          // holds V^T: [DIM][MTOT]
__device__ float g_S[(size_t)BATCH * SEQ * SEQ];
__device__ float g_X[(size_t)MTOT * DIM];          // tf32-rounded x
__device__ float g_W[(size_t)3 * DIM * DIM];       // tf32-rounded [Wq;Wk;Wv]

// ---------------------------------------------------------------------------
static __device__ __forceinline__ uint32_t s2u(const void* p) {
    uint32_t a;
    asm("{ .reg .u64 t; cvta.to.shared.u64 t, %1; cvt.u32.u64 %0, t; }"
        : "=r"(a) : "l"(p));
    return a;
}
static __device__ __forceinline__ uint32_t f2tf32(float f) {
    uint32_t r;
    asm("cvt.rna.tf32.f32 %0, %1;" : "=r"(r) : "f"(f));
    return r;
}
static __device__ __forceinline__ float rtf(float f) {
    return __uint_as_float(f2tf32(f));
}
static __device__ __forceinline__ void cpasync16(uint32_t saddr, const void* gaddr) {
    asm volatile("cp.async.cg.shared.global [%0], [%1], 16;"
                 :: "r"(saddr), "l"(gaddr) : "memory");
}
static __device__ __forceinline__ void cpcommit() {
    asm volatile("cp.async.commit_group;" ::: "memory");
}
static __device__ __forceinline__ void cpwait0() {
    asm volatile("cp.async.wait_group 0;" ::: "memory");
}
static __device__ __forceinline__ void cpwait1() {
    asm volatile("cp.async.wait_group 1;" ::: "memory");
}
static __device__ __forceinline__ void mma_tf32(float* c, uint32_t a0, uint32_t a1,
                                                uint32_t a2, uint32_t a3,
                                                uint32_t b0, uint32_t b1) {
    asm volatile(
        "mma.sync.aligned.m16n8k8.row.col.f32.tf32.tf32.f32 "
        "{%0,%1,%2,%3}, {%4,%5,%6,%7}, {%8,%9}, {%0,%1,%2,%3};"
        : "+f"(c[0]), "+f"(c[1]), "+f"(c[2]), "+f"(c[3])
        : "r"(a0), "r"(a1), "r"(a2), "r"(a3), "r"(b0), "r"(b1));
}
// Row-swizzle function for 16B chunks within a 128B row.
static __device__ __forceinline__ int swzf(int r) {
    return 2 * (r & 3) + ((r >> 2) & 1);
}

// ---------------------------------------------------------------------------
// Pre-round x to tf32 (rna), float4 granularity.
// ---------------------------------------------------------------------------
__global__ void __launch_bounds__(256)
round_tf32(const float4* __restrict__ in, float4* __restrict__ out, int n4)
{
    int i = blockIdx.x * 256 + threadIdx.x;
    if (i < n4) {
        float4 v = in[i];
        out[i] = make_float4(rtf(v.x), rtf(v.y), rtf(v.z), rtf(v.w));
    }
}

// Round the 3 weight matrices into concatenated g_W in one launch.
__global__ void __launch_bounds__(256)
round_w3(const float4* __restrict__ wq, const float4* __restrict__ wk,
         const float4* __restrict__ wv, float4* __restrict__ out, int n4)
{
    int i = blockIdx.x * 256 + threadIdx.x;
    if (i >= n4) return;
    const float4* src = (blockIdx.y == 0) ? wq : (blockIdx.y == 1) ? wk : wv;
    float4 v = src[i];
    out[(size_t)blockIdx.y * n4 + i] =
        make_float4(rtf(v.x), rtf(v.y), rtf(v.z), rtf(v.w));
}

// ---------------------------------------------------------------------------
// tf32 mma.sync NT GEMM: C[m][n] = alpha * sum_k A[m][k] * B[n][k]
// Inputs must already be tf32-rounded. 3-stage cp.async pipeline (wait_group 1,
// 2-chunk prefetch distance), one __syncthreads per K-chunk. SMEM tiles are
// 128B/row with 16B-chunk XOR swizzle j^=f(row), f(r)=2(r&3)+((r>>2)&1) —
// conflict-free for both cp.async writes and LDS.64 fragment reads.
// k-pair bijection {t4,t4+4}->{2t4,2t4+1} unchanged (bit-identical to pad-40).
// flags: 1 = causal tile skip (n0 > m0), 2 = transposed epilogue (C[n][m]),
//        4 = causal K bound (kend = m0 + BM), 8 = round output to tf32,
//        16 = fused-QKV routing (n-tiles 0-7 -> C, 8-15 -> C2, 16-23 -> C3
//             transposed with ldc = MTOT)
//        32 = reversed m-tile order (longest causal K first; LPT packing)
// ---------------------------------------------------------------------------
__global__ void __launch_bounds__(NTHR, 2)
gemm_mma(const float* __restrict__ A, const float* __restrict__ B,
         float* __restrict__ C, float* __restrict__ C2, float* __restrict__ C3,
         int K, int lda, int ldb, int ldc,
         long sA, long sB, long sC, float alpha, int flags)
{
    const int my = (flags & 32) ? (gridDim.y - 1 - blockIdx.y) : blockIdx.y;
    const int m0 = my * BM;
    const int n0 = blockIdx.x * BN;          // B-space n origin
    if ((flags & 1) && n0 > m0) return;

    A += (long)blockIdx.z * sA;
    B += (long)blockIdx.z * sB;

    extern __shared__ float smf[];
    const uint32_t sa = s2u(smf);

    const int tid  = threadIdx.x;
    const int lane = tid & 31;
    const int w    = tid >> 5;
    const int wm   = (w >> 2) * 64;     // warp tile M origin (0 or 64)
    const int wn   = (w & 3) * 32;      // warp tile N origin (0..96)
    const int g    = lane >> 2;         // 0..7
    const int t4   = lane & 3;          // 0..3

    const int kend = (flags & 4) ? min(K, m0 + BM) : K;
    const int nc   = kend / BK;

    // Global->smem geometry: 4 x 16B cp.async per thread per operand per chunk
    const int lr  = tid >> 3;           // 0..31 base row
    const int lc4 = (tid & 7) * 4;      // float col 0,4,...,28 (nominal chunk)
    const int jw  = (tid & 7) ^ swzf(lr);   // swizzled write chunk (same all i)
    const float* Ag[4]; const float* Bg[4];
    uint32_t sob[4];                    // swizzled smem byte offset in a tile
    #pragma unroll
    for (int i = 0; i < 4; i++) {
        const int row = lr + 32 * i;
        Ag[i] = A + (long)(m0 + row) * lda + lc4;
        Bg[i] = B + (long)(n0 + row) * ldb + lc4;
        sob[i] = (uint32_t)(row * 128 + jw * 16);
    }

    // Fragment read constants (floats): row base + cb + kofs[ks]
    const int fg = swzf(g);
    const int cb = 4 * ((t4 >> 1) ^ (fg & 1)) + 2 * (t4 & 1);
    const int fh = fg >> 1;

    float acc[4][4][4];
    #pragma unroll
    for (int i = 0; i < 4; i++)
        #pragma unroll
        for (int j = 0; j < 4; j++)
            #pragma unroll
            for (int k = 0; k < 4; k++) acc[i][j][k] = 0.f;

    // prologue: chunk 0 -> stage 0, chunk 1 -> stage 1
    {
        #pragma unroll
        for (int i = 0; i < 4; i++) {
            cpasync16(sa + sob[i], Ag[i]);
            cpasync16(sa + TILE_BYTES + sob[i], Bg[i]);
            Ag[i] += BK; Bg[i] += BK;
        }
        cpcommit();
    }
    if (nc > 1) {
        const uint32_t st = 2u * TILE_BYTES;
        #pragma unroll
        for (int i = 0; i < 4; i++) {
            cpasync16(sa + st + sob[i], Ag[i]);
            cpasync16(sa + st + TILE_BYTES + sob[i], Bg[i]);
            Ag[i] += BK; Bg[i] += BK;
        }
        cpcommit();
    }

    int stage = 0;            // stage holding chunk c
    int wstage = 2;           // stage receiving chunk c+2
    for (int c = 0; c < nc; c++) {
        if (c + 1 < nc) cpwait1(); else cpwait0();   // group c complete
        __syncthreads();      // data visible; stage 'wstage' fully consumed

        if (c + 2 < nc) {
            const uint32_t st = (uint32_t)wstage * 2u * TILE_BYTES;
            #pragma unroll
            for (int i = 0; i < 4; i++) {
                cpasync16(sa + st + sob[i], Ag[i]);
                cpasync16(sa + st + TILE_BYTES + sob[i], Bg[i]);
                Ag[i] += BK; Bg[i] += BK;
            }
            cpcommit();
        }

        const float* Au = smf + stage * 2 * TILE_FLOATS;
        const float* Bu = Au + TILE_FLOATS;
        #pragma unroll
        for (int ks = 0; ks < 4; ks++) {
            const int kf = 8 * (ks ^ fh) + cb;   // swizzled k-offset (floats)
            uint32_t af[4][4];
            #pragma unroll
            for (int tm = 0; tm < 4; tm++) {
                const float* ar = Au + (wm + tm * 16 + g) * 32 + kf;
                uint2 lo = *(const uint2*)ar;
                uint2 hi = *(const uint2*)(ar + 256);   // +8 rows
                af[tm][0] = lo.x; af[tm][2] = lo.y;     // k=2t4, 2t4+1
                af[tm][1] = hi.x; af[tm][3] = hi.y;
            }
            uint32_t bf[4][2];
            #pragma unroll
            for (int tn = 0; tn < 4; tn++) {
                uint2 bv = *(const uint2*)(Bu + (wn + tn * 8 + g) * 32 + kf);
                bf[tn][0] = bv.x; bf[tn][1] = bv.y;
            }
            #pragma unroll
            for (int tm = 0; tm < 4; tm++)
                #pragma unroll
                for (int tn = 0; tn < 4; tn++)
                    mma_tf32(acc[tm][tn], af[tm][0], af[tm][1], af[tm][2],
                             af[tm][3], bf[tn][0], bf[tn][1]);
        }

        stage  = (stage == NSTAGE - 1) ? 0 : stage + 1;
        wstage = (wstage == NSTAGE - 1) ? 0 : wstage + 1;
    }

    // Output routing
    float* Cc = C;
    int  nc0  = n0;
    int  ldcc = ldc;
    bool trans = (flags & 2) != 0;
    if (flags & 16) {
        const int ci = blockIdx.x >> 3;
        nc0 = (blockIdx.x & 7) * BN;
        if (ci == 1)      Cc = C2;
        else if (ci == 2) { Cc = C3; trans = true; ldcc = MTOT; }
    }
    Cc += (long)blockIdx.z * sC;

    const bool rnd = (flags & 8) != 0;
    if (trans) {
        #pragma unroll
        for (int tm = 0; tm < 4; tm++) {
            const int mA = m0 + wm + tm * 16 + g;
            #pragma unroll
            for (int tn = 0; tn < 4; tn++) {
                const int n = nc0 + wn + tn * 8 + t4 * 2;
                float v0 = alpha * acc[tm][tn][0], v1 = alpha * acc[tm][tn][1];
                float v2 = alpha * acc[tm][tn][2], v3 = alpha * acc[tm][tn][3];
                if (rnd) { v0 = rtf(v0); v1 = rtf(v1); v2 = rtf(v2); v3 = rtf(v3); }
                Cc[(long)n * ldcc + mA]           = v0;
                Cc[(long)(n + 1) * ldcc + mA]     = v1;
                Cc[(long)n * ldcc + mA + 8]       = v2;
                Cc[(long)(n + 1) * ldcc + mA + 8] = v3;
            }
        }
    } else {
        #pragma unroll
        for (int tm = 0; tm < 4; tm++) {
            const int mA = m0 + wm + tm * 16 + g;
            #pragma unroll
            for (int tn = 0; tn < 4; tn++) {
                const int n = nc0 + wn + tn * 8 + t4 * 2;
                float v0 = alpha * acc[tm][tn][0], v1 = alpha * acc[tm][tn][1];
                float v2 = alpha * acc[tm][tn][2], v3 = alpha * acc[tm][tn][3];
                if (rnd) { v0 = rtf(v0); v1 = rtf(v1); v2 = rtf(v2); v3 = rtf(v3); }
                *(float2*)(Cc + (long)mA * ldcc + n)       = make_float2(v0, v1);
                *(float2*)(Cc + (long)(mA + 8) * ldcc + n) = make_float2(v2, v3);
            }
        }
    }
}

// ---------------------------------------------------------------------------
// Causal row softmax, in place. float4 traffic + shuffle reductions.
// Writes tf32-rounded P and zero-fills (q, 128-tile boundary).
// ---------------------------------------------------------------------------
__global__ void __launch_bounds__(256)
softmax_causal(float* __restrict__ S_, int S)
{
    const long row = blockIdx.x;            // b*S + q
    const int  q   = (int)(row & (long)(S - 1));
    float* p = S_ + row * (long)S;
    const int n = q + 1;
    const int n4 = n >> 2;                  // full float4s
    const int nr = n & 3;                   // tail elements

    __shared__ float buf[SEQ];
    __shared__ float red[8];
    float4* const p4   = (float4*)p;
    float4* const buf4 = (float4*)buf;
    const int tid  = threadIdx.x;
    const int lane = tid & 31;
    const int wid  = tid >> 5;

    // pass 1: load + max
    float lmax = -3.4e38f;
    for (int i = tid; i < n4; i += 256) {
        float4 v = p4[i];
        buf4[i] = v;
        lmax = fmaxf(fmaxf(lmax, fmaxf(v.x, v.y)), fmaxf(v.z, v.w));
    }
    if (tid < nr) {
        float v = p[n4 * 4 + tid];
        buf[n4 * 4 + tid] = v;
        lmax = fmaxf(lmax, v);
    }
    #pragma unroll
    for (int s = 16; s > 0; s >>= 1)
        lmax = fmaxf(lmax, __shfl_xor_sync(0xffffffffu, lmax, s));
    if (lane == 0) red[wid] = lmax;
    __syncthreads();
    float m = red[0];
    #pragma unroll
    for (int i = 1; i < 8; i++) m = fmaxf(m, red[i]);
    __syncthreads();

    // pass 2: exp + sum (in smem)
    float lsum = 0.f;
    for (int i = tid; i < n4; i += 256) {
        float4 v = buf4[i];
        v.x = __expf(v.x - m); v.y = __expf(v.y - m);
        v.z = __expf(v.z - m); v.w = __expf(v.w - m);
        buf4[i] = v;
        lsum += (v.x + v.y) + (v.z + v.w);
    }
    if (tid < nr) {
        float e = __expf(buf[n4 * 4 + tid] - m);
        buf[n4 * 4 + tid] = e;
        lsum += e;
    }
    #pragma unroll
    for (int s = 16; s > 0; s >>= 1)
        lsum += __shfl_xor_sync(0xffffffffu, lsum, s);
    if (lane == 0) red[wid] = lsum;
    __syncthreads();
    float tot = 0.f;
    #pragma unroll
    for (int i = 0; i < 8; i++) tot += red[i];
    const float inv = 1.0f / tot;

    // pass 3: normalize + tf32-round + store; zero-fill to tile boundary
    for (int i = tid; i < n4; i += 256) {
        float4 v = buf4[i];
        p4[i] = make_float4(rtf(v.x * inv), rtf(v.y * inv),
                            rtf(v.z * inv), rtf(v.w * inv));
    }
    if (tid < nr) p[n4 * 4 + tid] = rtf(buf[n4 * 4 + tid] * inv);
    const int zend = ((q >> 7) + 1) << 7;   // next multiple of BM=128
    for (int i = n + tid; i < zend; i += 256) p[i] = 0.f;
}

// ---------------------------------------------------------------------------
extern "C" void kernel_launch(void* const* d_in, const int* in_sizes, int n_in,
                              void* d_out, int out_size)
{
    const float* x  = (const float*)d_in[0];
    const float* Wq = (const float*)d_in[1];
    const float* Wk = (const float*)d_in[2];
    const float* Wv = (const float*)d_in[3];
    float* out = (float*)d_out;

    float *Q, *Kd, *Vt, *Sc, *Xr, *Wc;
    cudaGetSymbolAddress((void**)&Q,  g_Q);
    cudaGetSymbolAddress((void**)&Kd, g_K);
    cudaGetSymbolAddress((void**)&Vt, g_V);
    cudaGetSymbolAddress((void**)&Sc, g_S);
    cudaGetSymbolAddress((void**)&Xr, g_X);
    cudaGetSymbolAddress((void**)&Wc, g_W);

    cudaFuncSetAttribute(gemm_mma, cudaFuncAttributeMaxDynamicSharedMemorySize,
                         SMEM_DYN);

    // tf32-round inputs; weights concatenated into g_W = [Wq;Wk;Wv]
    const int nx4 = (MTOT * DIM) / 4, nw4 = (DIM * DIM) / 4;
    round_tf32<<<(nx4 + 255) / 256, 256>>>((const float4*)x, (float4*)Xr, nx4);
    {
        dim3 gW((nw4 + 255) / 256, 3, 1);
        round_w3<<<gW, 256>>>((const float4*)Wq, (const float4*)Wk,
                              (const float4*)Wv, (float4*)Wc, nw4);
    }

    // Fused QKV projection: N = 3072 over concatenated weights.
    // n-tiles 0-7 -> Q, 8-15 -> K, 16-23 -> V^T (transposed, ldc=MTOT)
    dim3 gP(3 * DIM / BN, MTOT / BM, 1);
    gemm_mma<<<gP, NTHR, SMEM_DYN>>>(Xr, Wc, Q, Kd, Vt,
                                     DIM, DIM, DIM, DIM,
                                     0, 0, 0, 1.0f, 8 | 16);

    // scores = (1/32) * Q K^T per batch, causal tile skip (no rounding)
    const long sQK = (long)SEQ * DIM;
    const long sSS = (long)SEQ * SEQ;
    dim3 gS(SEQ / BN, SEQ / BM, BATCH);
    gemm_mma<<<gS, NTHR, SMEM_DYN>>>(Q, Kd, Sc, Sc, Sc,
                                     DIM, DIM, DIM, SEQ,
                                     sQK, sQK, sSS, 0.03125f, 1);

    softmax_causal<<<BATCH * SEQ, 256>>>(Sc, SEQ);

    // out = P V per batch : NT with B = Vt (ldb = MTOT), causal K bound.
    // Reversed m-tile order (flag 32): longest-K tiles launch first (LPT).
    dim3 gPV(DIM / BN, SEQ / BM, BATCH);
    gemm_mma<<<gPV, NTHR, SMEM_DYN>>>(Sc, Vt, out, out, out,
                                      SEQ, SEQ, MTOT, DIM,
                                      sSS, (long)SEQ, sQK, 1.0f, 4 | 32);
}